// round 16
// baseline (speedup 1.0000x reference)
#include <cuda_runtime.h>
#include <cstdint>

// ---------------------------------------------------------------------------
// AttentionHead  B=8 S=4096 D=1024 DK=64
// Round 16: attn warp tile widened to 32 q-rows x 64 kv (256-thread CTAs,
// ~224 regs) -> every K/V B-fragment amortized over 2 MMA sets; per-SM LDS
// per tile halves (4.1k -> 2.0k cyc) under unchanged 4.1k tensor work.
// Structure else = R15 (de-lockstep halves, reg-resident P, pairing, skip).
// proj / w_round = R15 verbatim.
// ---------------------------------------------------------------------------

constexpr int B  = 8;
constexpr int S  = 4096;
constexpr int D  = 1024;
constexpr int DK = 64;
constexpr int M  = B * S;

__device__ float g_Q[M * DK];
__device__ float g_K[M * DK];
__device__ float g_V[M * DK];    // used as [B][64][4096], t pair-permuted
__device__ float g_Wr[192 * D];  // tf32-exact [wQ|wK|wV]

__device__ __forceinline__ float ex2f(float x) {
    float y; asm("ex2.approx.ftz.f32 %0, %1;" : "=f"(y) : "f"(x)); return y;
}
__device__ __forceinline__ uint32_t tf32_rna(float f) {
    uint32_t u; asm("cvt.rna.tf32.f32 %0, %1;" : "=r"(u) : "f"(f)); return u;
}
__device__ __forceinline__ float tf32ef(float f) {
    return __uint_as_float(tf32_rna(f));
}
__device__ __forceinline__ uint32_t f2u(float f) { return __float_as_uint(f); }

__host__ __device__ __forceinline__ int perm8(int u) {
    return 2 * (u & 3) + ((u >> 2) & 1);
}

__device__ __forceinline__ void cpa16(void* dst_smem, const void* src) {
    uint32_t a;
    asm("{ .reg .u64 t; cvta.to.shared.u64 t, %1; cvt.u32.u64 %0, t; }"
        : "=r"(a) : "l"(dst_smem));
    asm volatile("cp.async.cg.shared.global [%0], [%1], 16;" :: "r"(a), "l"(src));
}
#define CPA_COMMIT() asm volatile("cp.async.commit_group;" ::: "memory")
template <int N>
__device__ __forceinline__ void cpa_wait() {
    asm volatile("cp.async.wait_group %0;" :: "n"(N) : "memory");
}
#define BAR_SYNC128(id) asm volatile("bar.sync %0, 128;" :: "r"(id) : "memory")

__device__ __forceinline__ void mma8(float c[4], const uint32_t a[4],
                                     uint32_t b0, uint32_t b1) {
    asm volatile(
        "mma.sync.aligned.m16n8k8.row.col.f32.tf32.tf32.f32 "
        "{%0,%1,%2,%3}, {%4,%5,%6,%7}, {%8,%9}, {%0,%1,%2,%3};"
        : "+f"(c[0]), "+f"(c[1]), "+f"(c[2]), "+f"(c[3])
        : "r"(a[0]), "r"(a[1]), "r"(a[2]), "r"(a[3]), "r"(b0), "r"(b1));
}

constexpr float NEG = -1e30f;

// ---------------------------------------------------------------------------
// Phase 0: round W once to tf32-exact fp32 (float4 per thread)
// ---------------------------------------------------------------------------
__global__ void w_round_kernel(const float* __restrict__ wq,
                               const float* __restrict__ wk,
                               const float* __restrict__ wv)
{
    int base = (blockIdx.x * 256 + threadIdx.x) * 4;
    int n = base >> 10;
    const float* w = (n < 64) ? wq : (n < 128) ? wk : wv;
    float4 v = *(const float4*)(w + (size_t)(n & 63) * D + (base & 1023));
    *(float4*)(g_Wr + base) = make_float4(tf32ef(v.x), tf32ef(v.y),
                                          tf32ef(v.z), tf32ef(v.w));
}

// ---------------------------------------------------------------------------
// Phase 1: C[M,192] = X[M,1024] @ Wr^T   (R15 verbatim)
// ---------------------------------------------------------------------------
constexpr int PXS = 256 * 36;
constexpr int PWS = 192 * 36;
constexpr int PSTG = PXS + PWS;
constexpr int PROJ_SMEM = 2 * PSTG * 4;

__global__ __launch_bounds__(512, 1)
void proj_kernel(const float* __restrict__ x)
{
    extern __shared__ float ps[];
    const int tid  = threadIdx.x;
    const int lane = tid & 31;
    const int warp = tid >> 5;
    const int wm   = warp & 7;
    const int wn   = warp >> 3;
    const int m0   = blockIdx.x * 256;

    auto load_stage = [&](int st, int k0) {
        float* xs = ps + st * PSTG;
        float* ws = xs + PXS;
#pragma unroll
        for (int p = 0; p < 4; p++) {
            int c = tid + p * 512;
            int t = c >> 3, seg = c & 7;
            cpa16(xs + t * 36 + seg * 4, x + (size_t)(m0 + t) * D + k0 + seg * 4);
        }
#pragma unroll
        for (int p = 0; p < 3; p++) {
            int c = tid + p * 512;
            int n = c >> 3, seg = c & 7;
            cpa16(ws + n * 36 + seg * 4, g_Wr + (size_t)n * D + k0 + seg * 4);
        }
        CPA_COMMIT();
    };

    float acc[2][12][4];
#pragma unroll
    for (int mt = 0; mt < 2; mt++)
#pragma unroll
        for (int nt = 0; nt < 12; nt++)
#pragma unroll
            for (int e = 0; e < 4; e++) acc[mt][nt][e] = 0.0f;

    load_stage(0, 0);

    for (int it = 0; it < 32; ++it) {
        cpa_wait<0>();
        __syncthreads();
        if (it + 1 < 32) load_stage((it + 1) & 1, (it + 1) * 32);

        const float* xs = ps + (it & 1) * PSTG;
        const float* ws = xs + PXS;
        const float* aB = xs + (wm * 32 + (lane >> 2)) * 36 + (lane & 3);
        const float* bB = ws + (wn * 96 + (lane >> 2)) * 36 + (lane & 3);

#pragma unroll
        for (int s = 0; s < 4; s++) {
            uint32_t a[2][4];
#pragma unroll
            for (int mt = 0; mt < 2; mt++) {
                const float* ap = aB + mt * 16 * 36 + s * 8;
                a[mt][0] = tf32_rna(ap[0]);
                a[mt][1] = tf32_rna(ap[8 * 36]);
                a[mt][2] = tf32_rna(ap[4]);
                a[mt][3] = tf32_rna(ap[8 * 36 + 4]);
            }
#pragma unroll
            for (int nt = 0; nt < 12; nt++) {
                const float* bp = bB + nt * 8 * 36 + s * 8;
                uint32_t b0 = f2u(bp[0]);
                uint32_t b1 = f2u(bp[4]);
                mma8(acc[0][nt], a[0], b0, b1);
                mma8(acc[1][nt], a[1], b0, b1);
            }
        }
    }

    const float SC = (float)(1.4426950408889634 / 32.0);
#pragma unroll
    for (int mt = 0; mt < 2; mt++) {
#pragma unroll
        for (int nt = 0; nt < 12; nt++) {
            int col = wn * 96 + nt * 8 + 2 * (lane & 3);
            int row = m0 + wm * 32 + mt * 16 + (lane >> 2);
            if (col < 128) {
                float* outp = (col < 64) ? g_Q : g_K;
                float sc = (col < 64) ? SC : 1.0f;
                int b8  = (col & 63) & ~7;
                int p0  = b8 | perm8(col & 7);
                int p1  = b8 | perm8((col + 1) & 7);
                outp[(size_t)row * DK + p0]       = tf32ef(acc[mt][nt][0] * sc);
                outp[(size_t)row * DK + p1]       = tf32ef(acc[mt][nt][1] * sc);
                outp[(size_t)(row + 8) * DK + p0] = tf32ef(acc[mt][nt][2] * sc);
                outp[(size_t)(row + 8) * DK + p1] = tf32ef(acc[mt][nt][3] * sc);
            } else {
                int lc = col & 63;
                int b0r = row >> 12,  s0 = row & 4095;
                int b1r = (row + 8) >> 12, s1 = (row + 8) & 4095;
                size_t pt0 = (size_t)(s0 & ~7) | perm8(s0 & 7);
                size_t pt1 = (size_t)(s1 & ~7) | perm8(s1 & 7);
                g_V[((size_t)b0r * 64 + lc)     * 4096 + pt0] = tf32ef(acc[mt][nt][0]);
                g_V[((size_t)b0r * 64 + lc + 1) * 4096 + pt0] = tf32ef(acc[mt][nt][1]);
                g_V[((size_t)b1r * 64 + lc)     * 4096 + pt1] = tf32ef(acc[mt][nt][2]);
                g_V[((size_t)b1r * 64 + lc + 1) * 4096 + pt1] = tf32ef(acc[mt][nt][3]);
            }
        }
    }
}

// ---------------------------------------------------------------------------
// Phase 2: flash attention, 256 thr = 4 row-groups(32q) x 2 kv-halves(64).
// Each warp: 2 MMA sets (16 q-rows each) sharing every K/V B-fragment.
// De-lockstepped halves on 128-thread named barriers; register-resident P.
// ---------------------------------------------------------------------------
constexpr int KSZ  = 128 * 72;
constexpr int VTSZ = 64 * 136;
constexpr int STG  = KSZ + VTSZ;
constexpr int COFF = 2 * STG;
constexpr int CSZ  = 128 * 132;
constexpr int ATTN_SMEM = (COFF + CSZ) * 4;   // 210944 B

__global__ __launch_bounds__(256, 1)
void attn_kernel(float* __restrict__ out)
{
    extern __shared__ float sm[];
    __shared__ float Xm[128];
    __shared__ float Xl[128];

    const int b    = blockIdx.y;
    const int pj   = blockIdx.x;
    const int tid  = threadIdx.x;
    const int lane = tid & 31;
    const int warp = tid >> 5;
    const int wc   = warp & 1;                // kv half
    const int wr   = warp >> 1;               // row group 0..3 (32 q-rows)
    const int wb   = wr * 32;
    const int kb   = wc * 64;
    const int p4   = lane >> 2;
    const int q4   = lane & 3;
    const int htid = (wr << 5) | lane;        // 0..127 within half
    const int barid = 1 + wc;

    float* Cs = sm + COFF;

    auto load_kv = [&](int kt, int st) {
        float* Ks  = sm + st * STG;
        float* VTs = Ks + KSZ;
        const int t0 = kt * 128;
#pragma unroll
        for (int p = 0; p < 8; p++) {         // K: 64 rows x 64 dk = 1024 chunks
            int c = htid + p * 128;
            int tl = c >> 4, seg = c & 15;
            int slot = kb + ((tl & ~7) | perm8(tl & 7));
            cpa16(Ks + slot * 72 + seg * 4,
                  g_K + ((size_t)(b * S + t0 + kb + tl)) * 64 + seg * 4);
        }
#pragma unroll
        for (int p = 0; p < 8; p++) {         // VT: 64 dk x 64 t = 1024 chunks
            int c = htid + p * 128;
            int dk = c >> 4, ch = c & 15;
            cpa16(VTs + dk * 136 + kb + ch * 4,
                  g_V + ((size_t)b * 64 + dk) * 4096 + t0 + kb + ch * 4);
        }
        CPA_COMMIT();
    };

    for (int qsel = 0; qsel < 2; qsel++) {
        const int qt = qsel ? (31 - pj) : pj;
        const int q0 = qt * 128;
        const int nt = qt + 1;

        load_kv(0, 0);

        // Q a-frags: 2 sets of 16 rows (wb+g*16 .. +15)
        uint32_t qa[2][8][4];
#pragma unroll
        for (int g = 0; g < 2; g++)
#pragma unroll
            for (int s = 0; s < 8; s++) {
                const float* qp = g_Q +
                    ((size_t)(b * S + q0 + wb + g * 16 + p4)) * 64 + s * 8 + 2 * q4;
                float2 lo = *(const float2*)qp;
                float2 hi = *(const float2*)(qp + 8 * 64);
                qa[g][s][0] = f2u(lo.x);
                qa[g][s][1] = f2u(hi.x);
                qa[g][s][2] = f2u(lo.y);
                qa[g][s][3] = f2u(hi.y);
            }

        float of[2][8][4];
        float mr[4], lr[4];
#pragma unroll
        for (int g = 0; g < 2; g++)
#pragma unroll
            for (int j = 0; j < 8; j++)
#pragma unroll
                for (int e = 0; e < 4; e++) of[g][j][e] = 0.0f;
#pragma unroll
        for (int e = 0; e < 4; e++) { mr[e] = NEG; lr[e] = 0.0f; }

        for (int it = 0; it < nt; ++it) {
            const int st = it & 1;
            cpa_wait<0>();
            BAR_SYNC128(barid);
            if (it + 1 < nt) load_kv(it + 1, st ^ 1);

            if (it == qt && kb > wb + 31) continue;   // fully-masked quarter

            const float* Ks  = sm + st * STG;
            const float* VTs = Ks + KSZ;

            // ---- S = Q K^T (K B-frag shared by both sets) ----
            float sf[2][8][4];
#pragma unroll
            for (int g = 0; g < 2; g++)
#pragma unroll
                for (int j = 0; j < 8; j++)
#pragma unroll
                    for (int e = 0; e < 4; e++) sf[g][j][e] = 0.0f;

            const float* kB = Ks + (kb + p4) * 72 + 2 * q4;
#pragma unroll
            for (int s = 0; s < 8; s++) {
                const float* kp = kB + s * 8;
#pragma unroll
                for (int j = 0; j < 8; j++) {
                    float2 kv2 = *(const float2*)(kp + j * 8 * 72);
                    uint32_t b0 = f2u(kv2.x), b1 = f2u(kv2.y);
                    mma8(sf[0][j], qa[0][s], b0, b1);
                    mma8(sf[1][j], qa[1][s], b0, b1);
                }
            }

            // ---- causal mask (diagonal tile) ----
            if (it == qt) {
#pragma unroll
                for (int g = 0; g < 2; g++) {
                    int r0 = wb + g * 16 + p4;
#pragma unroll
                    for (int j = 0; j < 8; j++) {
                        int ta = kb + j * 8 + q4;
                        int tb = ta + 4;
                        if (ta > r0)     sf[g][j][0] = NEG;
                        if (tb > r0)     sf[g][j][1] = NEG;
                        if (ta > r0 + 8) sf[g][j][2] = NEG;
                        if (tb > r0 + 8) sf[g][j][3] = NEG;
                    }
                }
            }

            // ---- warp-local online softmax (4 row sub-sets) ----
            float mx[4] = {NEG, NEG, NEG, NEG};
#pragma unroll
            for (int g = 0; g < 2; g++)
#pragma unroll
                for (int j = 0; j < 8; j++) {
                    mx[2 * g]     = fmaxf(mx[2 * g],     fmaxf(sf[g][j][0], sf[g][j][1]));
                    mx[2 * g + 1] = fmaxf(mx[2 * g + 1], fmaxf(sf[g][j][2], sf[g][j][3]));
                }
            float al[4];
#pragma unroll
            for (int e = 0; e < 4; e++) {
                mx[e] = fmaxf(mx[e], __shfl_xor_sync(0xffffffffu, mx[e], 1));
                mx[e] = fmaxf(mx[e], __shfl_xor_sync(0xffffffffu, mx[e], 2));
                float mn = fmaxf(mr[e], mx[e]);
                al[e] = ex2f(mr[e] - mn);
                mr[e] = mn;
            }
#pragma unroll
            for (int g = 0; g < 2; g++)
#pragma unroll
                for (int j = 0; j < 8; j++) {
                    of[g][j][0] *= al[2 * g];     of[g][j][1] *= al[2 * g];
                    of[g][j][2] *= al[2 * g + 1]; of[g][j][3] *= al[2 * g + 1];
                }

            // ---- exp + PV (V B-frag shared by both sets) ----
            float rs[4] = {0.0f, 0.0f, 0.0f, 0.0f};
            const float* vB = VTs + p4 * 136 + kb + 2 * q4;
#pragma unroll
            for (int s2 = 0; s2 < 8; s2++) {
                uint32_t pa[2][4];
#pragma unroll
                for (int g = 0; g < 2; g++) {
                    float p00 = tf32ef(ex2f(sf[g][s2][0] - mr[2 * g]));
                    float p01 = tf32ef(ex2f(sf[g][s2][1] - mr[2 * g]));
                    float p10 = tf32ef(ex2f(sf[g][s2][2] - mr[2 * g + 1]));
                    float p11 = tf32ef(ex2f(sf[g][s2][3] - mr[2 * g + 1]));
                    rs[2 * g]     += p00 + p01;
                    rs[2 * g + 1] += p10 + p11;
                    pa[g][0] = f2u(p00); pa[g][1] = f2u(p10);
                    pa[g][2] = f2u(p01); pa[g][3] = f2u(p11);
                }
                const float* vp = vB + s2 * 8;
#pragma unroll
                for (int j2 = 0; j2 < 8; j2++) {
                    float2 vv = *(const float2*)(vp + j2 * 8 * 136);
                    uint32_t b0 = f2u(vv.x), b1 = f2u(vv.y);
                    mma8(of[0][j2], pa[0], b0, b1);
                    mma8(of[1][j2], pa[1], b0, b1);
                }
            }
#pragma unroll
            for (int e = 0; e < 4; e++) {
                rs[e] += __shfl_xor_sync(0xffffffffu, rs[e], 1);
                rs[e] += __shfl_xor_sync(0xffffffffu, rs[e], 2);
                lr[e] = lr[e] * al[e] + rs[e];
            }
        }

        // ---- merge halves once per q-tile (exact LSE combine) ----
        __syncthreads();
        if (wc == 1) {
#pragma unroll
            for (int g = 0; g < 2; g++) {
                float* cb = Cs + (wb + g * 16 + p4) * 132 + 2 * q4;
#pragma unroll
                for (int j2 = 0; j2 < 8; j2++) {
                    *(float2*)(cb + j2 * 8) =
                        make_float2(of[g][j2][0], of[g][j2][1]);
                    *(float2*)(cb + 8 * 132 + j2 * 8) =
                        make_float2(of[g][j2][2], of[g][j2][3]);
                }
                if (q4 == 0) {
                    Xm[wb + g * 16 + p4]     = mr[2 * g];
                    Xl[wb + g * 16 + p4]     = lr[2 * g];
                    Xm[wb + g * 16 + p4 + 8] = mr[2 * g + 1];
                    Xl[wb + g * 16 + p4 + 8] = lr[2 * g + 1];
                }
            }
        }
        __syncthreads();
        if (wc == 0) {
#pragma unroll
            for (int g = 0; g < 2; g++) {
                float mo0 = Xm[wb + g * 16 + p4],     lo0 = Xl[wb + g * 16 + p4];
                float mo1 = Xm[wb + g * 16 + p4 + 8], lo1 = Xl[wb + g * 16 + p4 + 8];
                float mg0 = fmaxf(mr[2 * g], mo0), mg1 = fmaxf(mr[2 * g + 1], mo1);
                float s0 = ex2f(mr[2 * g] - mg0),     t0 = ex2f(mo0 - mg0);
                float s1 = ex2f(mr[2 * g + 1] - mg1), t1 = ex2f(mo1 - mg1);
                float inv0 = 1.0f / (lr[2 * g] * s0 + lo0 * t0);
                float inv1 = 1.0f / (lr[2 * g + 1] * s1 + lo1 * t1);
                const float* cb = Cs + (wb + g * 16 + p4) * 132 + 2 * q4;
                float* orow0 = out +
                    ((size_t)(b * S + q0 + wb + g * 16 + p4)) * 64 + 2 * q4;
                float* orow1 = orow0 + 8 * 64;
#pragma unroll
                for (int j2 = 0; j2 < 8; j2++) {
                    float2 c0 = *(const float2*)(cb + j2 * 8);
                    float2 c1 = *(const float2*)(cb + 8 * 132 + j2 * 8);
                    *(float2*)(orow0 + j2 * 8) =
                        make_float2((of[g][j2][0] * s0 + c0.x * t0) * inv0,
                                    (of[g][j2][1] * s0 + c0.y * t0) * inv0);
                    *(float2*)(orow1 + j2 * 8) =
                        make_float2((of[g][j2][2] * s1 + c1.x * t1) * inv1,
                                    (of[g][j2][3] * s1 + c1.y * t1) * inv1);
                }
            }
        }
        __syncthreads();
    }
}

// ---------------------------------------------------------------------------
extern "C" void kernel_launch(void* const* d_in, const int* in_sizes, int n_in,
                              void* d_out, int out_size)
{
    const float* x  = (const float*)d_in[0];
    const float* wq = (const float*)d_in[1];
    const float* wk = (const float*)d_in[2];
    const float* wv = (const float*)d_in[3];
    float* out = (float*)d_out;

    cudaFuncSetAttribute(proj_kernel,
                         cudaFuncAttributeMaxDynamicSharedMemorySize, PROJ_SMEM);
    cudaFuncSetAttribute(attn_kernel,
                         cudaFuncAttributeMaxDynamicSharedMemorySize, ATTN_SMEM);

    w_round_kernel<<<192, 256>>>(wq, wk, wv);
    proj_kernel<<<M / 256, 512, PROJ_SMEM>>>(x);
    attn_kernel<<<dim3(16, B), 256, ATTN_SMEM>>>(out);
}

// round 17
// speedup vs baseline: 1.0808x; 1.0808x over previous
#include <cuda_runtime.h>
#include <cstdint>

// ---------------------------------------------------------------------------
// AttentionHead  B=8 S=4096 D=1024 DK=64
// Round 17: attn reverted to R15 verbatim (R16 wide-warp regressed).
// proj: 128x192 tile, 256 threads, __launch_bounds__(256,2) -> 2 CTAs/SM
// (regs fit now that B-side CVTs are gone); two independent barrier domains
// per SM hide skew/CVT/LDS bubbles without duplicating W traffic.
// ---------------------------------------------------------------------------

constexpr int B  = 8;
constexpr int S  = 4096;
constexpr int D  = 1024;
constexpr int DK = 64;
constexpr int M  = B * S;

__device__ float g_Q[M * DK];
__device__ float g_K[M * DK];
__device__ float g_V[M * DK];    // used as [B][64][4096], t pair-permuted
__device__ float g_Wr[192 * D];  // tf32-exact [wQ|wK|wV]

__device__ __forceinline__ float ex2f(float x) {
    float y; asm("ex2.approx.ftz.f32 %0, %1;" : "=f"(y) : "f"(x)); return y;
}
__device__ __forceinline__ uint32_t tf32_rna(float f) {
    uint32_t u; asm("cvt.rna.tf32.f32 %0, %1;" : "=r"(u) : "f"(f)); return u;
}
__device__ __forceinline__ float tf32ef(float f) {
    return __uint_as_float(tf32_rna(f));
}
__device__ __forceinline__ uint32_t f2u(float f) { return __float_as_uint(f); }

__host__ __device__ __forceinline__ int perm8(int u) {
    return 2 * (u & 3) + ((u >> 2) & 1);
}

__device__ __forceinline__ void cpa16(void* dst_smem, const void* src) {
    uint32_t a;
    asm("{ .reg .u64 t; cvta.to.shared.u64 t, %1; cvt.u32.u64 %0, t; }"
        : "=r"(a) : "l"(dst_smem));
    asm volatile("cp.async.cg.shared.global [%0], [%1], 16;" :: "r"(a), "l"(src));
}
#define CPA_COMMIT() asm volatile("cp.async.commit_group;" ::: "memory")
template <int N>
__device__ __forceinline__ void cpa_wait() {
    asm volatile("cp.async.wait_group %0;" :: "n"(N) : "memory");
}
#define BAR_SYNC(id) asm volatile("bar.sync %0, 256;" :: "r"(id) : "memory")

__device__ __forceinline__ void mma8(float c[4], const uint32_t a[4],
                                     uint32_t b0, uint32_t b1) {
    asm volatile(
        "mma.sync.aligned.m16n8k8.row.col.f32.tf32.tf32.f32 "
        "{%0,%1,%2,%3}, {%4,%5,%6,%7}, {%8,%9}, {%0,%1,%2,%3};"
        : "+f"(c[0]), "+f"(c[1]), "+f"(c[2]), "+f"(c[3])
        : "r"(a[0]), "r"(a[1]), "r"(a[2]), "r"(a[3]), "r"(b0), "r"(b1));
}

constexpr float NEG = -1e30f;

// ---------------------------------------------------------------------------
// Phase 0: round W once to tf32-exact fp32 (float4 per thread)
// ---------------------------------------------------------------------------
__global__ void w_round_kernel(const float* __restrict__ wq,
                               const float* __restrict__ wk,
                               const float* __restrict__ wv)
{
    int base = (blockIdx.x * 256 + threadIdx.x) * 4;
    int n = base >> 10;
    const float* w = (n < 64) ? wq : (n < 128) ? wk : wv;
    float4 v = *(const float4*)(w + (size_t)(n & 63) * D + (base & 1023));
    *(float4*)(g_Wr + base) = make_float4(tf32ef(v.x), tf32ef(v.y),
                                          tf32ef(v.z), tf32ef(v.w));
}

// ---------------------------------------------------------------------------
// Phase 1: C[M,192] = X[M,1024] @ Wr^T
// CTA 128x192, 256 thr (8 warps: 4M x 2N, warp 32x96), 2 CTAs/SM.
// Same per-element k-order as R15 -> bit-identical outputs.
// ---------------------------------------------------------------------------
constexpr int PXS = 128 * 36;
constexpr int PWS = 192 * 36;
constexpr int PSTG = PXS + PWS;               // 11520 floats
constexpr int PROJ_SMEM = 2 * PSTG * 4;       // 92160 B per CTA

__global__ __launch_bounds__(256, 2)
void proj_kernel(const float* __restrict__ x)
{
    extern __shared__ float ps[];
    const int tid  = threadIdx.x;
    const int lane = tid & 31;
    const int warp = tid >> 5;
    const int wm   = warp & 3;                // 4 M-groups of 32 rows
    const int wn   = warp >> 2;               // 2 N-groups of 96 cols
    const int m0   = blockIdx.x * 128;

    auto load_stage = [&](int st, int k0) {
        float* xs = ps + st * PSTG;
        float* ws = xs + PXS;
#pragma unroll
        for (int p = 0; p < 4; p++) {         // x: 128 rows x 32 f = 1024 chunks
            int c = tid + p * 256;
            int t = c >> 3, seg = c & 7;
            cpa16(xs + t * 36 + seg * 4, x + (size_t)(m0 + t) * D + k0 + seg * 4);
        }
#pragma unroll
        for (int p = 0; p < 6; p++) {         // Wr: 192 rows x 32 f = 1536 chunks
            int c = tid + p * 256;
            int n = c >> 3, seg = c & 7;
            cpa16(ws + n * 36 + seg * 4, g_Wr + (size_t)n * D + k0 + seg * 4);
        }
        CPA_COMMIT();
    };

    float acc[2][12][4];
#pragma unroll
    for (int mt = 0; mt < 2; mt++)
#pragma unroll
        for (int nt = 0; nt < 12; nt++)
#pragma unroll
            for (int e = 0; e < 4; e++) acc[mt][nt][e] = 0.0f;

    load_stage(0, 0);

    for (int it = 0; it < 32; ++it) {
        cpa_wait<0>();
        __syncthreads();
        if (it + 1 < 32) load_stage((it + 1) & 1, (it + 1) * 32);

        const float* xs = ps + (it & 1) * PSTG;
        const float* ws = xs + PXS;
        const float* aB = xs + (wm * 32 + (lane >> 2)) * 36 + (lane & 3);
        const float* bB = ws + (wn * 96 + (lane >> 2)) * 36 + (lane & 3);

#pragma unroll
        for (int s = 0; s < 4; s++) {
            uint32_t a[2][4];
#pragma unroll
            for (int mt = 0; mt < 2; mt++) {
                const float* ap = aB + mt * 16 * 36 + s * 8;
                a[mt][0] = tf32_rna(ap[0]);
                a[mt][1] = tf32_rna(ap[8 * 36]);
                a[mt][2] = tf32_rna(ap[4]);
                a[mt][3] = tf32_rna(ap[8 * 36 + 4]);
            }
#pragma unroll
            for (int nt = 0; nt < 12; nt++) {
                const float* bp = bB + nt * 8 * 36 + s * 8;
                uint32_t b0 = f2u(bp[0]);     // already tf32-exact
                uint32_t b1 = f2u(bp[4]);
                mma8(acc[0][nt], a[0], b0, b1);
                mma8(acc[1][nt], a[1], b0, b1);
            }
        }
    }

    // epilogue: Q scaled; tf32-exact outputs; permuted scratch layouts.
    const float SC = (float)(1.4426950408889634 / 32.0);
#pragma unroll
    for (int mt = 0; mt < 2; mt++) {
#pragma unroll
        for (int nt = 0; nt < 12; nt++) {
            int col = wn * 96 + nt * 8 + 2 * (lane & 3);
            int row = m0 + wm * 32 + mt * 16 + (lane >> 2);
            if (col < 128) {
                float* outp = (col < 64) ? g_Q : g_K;
                float sc = (col < 64) ? SC : 1.0f;
                int b8  = (col & 63) & ~7;
                int p0  = b8 | perm8(col & 7);
                int p1  = b8 | perm8((col + 1) & 7);
                outp[(size_t)row * DK + p0]       = tf32ef(acc[mt][nt][0] * sc);
                outp[(size_t)row * DK + p1]       = tf32ef(acc[mt][nt][1] * sc);
                outp[(size_t)(row + 8) * DK + p0] = tf32ef(acc[mt][nt][2] * sc);
                outp[(size_t)(row + 8) * DK + p1] = tf32ef(acc[mt][nt][3] * sc);
            } else {
                int lc = col & 63;
                int b0r = row >> 12,  s0 = row & 4095;
                int b1r = (row + 8) >> 12, s1 = (row + 8) & 4095;
                size_t pt0 = (size_t)(s0 & ~7) | perm8(s0 & 7);
                size_t pt1 = (size_t)(s1 & ~7) | perm8(s1 & 7);
                g_V[((size_t)b0r * 64 + lc)     * 4096 + pt0] = tf32ef(acc[mt][nt][0]);
                g_V[((size_t)b0r * 64 + lc + 1) * 4096 + pt0] = tf32ef(acc[mt][nt][1]);
                g_V[((size_t)b1r * 64 + lc)     * 4096 + pt1] = tf32ef(acc[mt][nt][2]);
                g_V[((size_t)b1r * 64 + lc + 1) * 4096 + pt1] = tf32ef(acc[mt][nt][3]);
            }
        }
    }
}

// ---------------------------------------------------------------------------
// Phase 2: flash attention (R15 verbatim): 128 causal-paired blocks, 512 thr,
// de-lockstepped kv-halves, register-resident P, diag-quarter skip, LSE merge.
// ---------------------------------------------------------------------------
constexpr int KSZ  = 128 * 72;
constexpr int VTSZ = 64 * 136;
constexpr int STG  = KSZ + VTSZ;
constexpr int COFF = 2 * STG;
constexpr int CSZ  = 128 * 132;
constexpr int ATTN_SMEM = (COFF + CSZ) * 4;   // 210944 B

__global__ __launch_bounds__(512, 1)
void attn_kernel(float* __restrict__ out)
{
    extern __shared__ float sm[];
    __shared__ float Xm[128];
    __shared__ float Xl[128];

    const int b    = blockIdx.y;
    const int pj   = blockIdx.x;
    const int tid  = threadIdx.x;
    const int lane = tid & 31;
    const int warp = tid >> 5;
    const int wc   = warp >> 3;
    const int wr   = warp & 7;
    const int wb   = wr * 16;
    const int kb   = wc * 64;
    const int p4   = lane >> 2;
    const int q4   = lane & 3;
    const int htid = tid & 255;
    const int barid = 1 + wc;

    float* Cs = sm + COFF;

    auto load_kv = [&](int kt, int st) {
        float* Ks  = sm + st * STG;
        float* VTs = Ks + KSZ;
        const int t0 = kt * 128;
#pragma unroll
        for (int p = 0; p < 4; p++) {
            int c = htid + p * 256;
            int tl = c >> 4, seg = c & 15;
            int slot = kb + ((tl & ~7) | perm8(tl & 7));
            cpa16(Ks + slot * 72 + seg * 4,
                  g_K + ((size_t)(b * S + t0 + kb + tl)) * 64 + seg * 4);
        }
#pragma unroll
        for (int p = 0; p < 4; p++) {
            int c = htid + p * 256;
            int dk = c >> 4, ch = c & 15;
            cpa16(VTs + dk * 136 + kb + ch * 4,
                  g_V + ((size_t)b * 64 + dk) * 4096 + t0 + kb + ch * 4);
        }
        CPA_COMMIT();
    };

    for (int qsel = 0; qsel < 2; qsel++) {
        const int qt = qsel ? (31 - pj) : pj;
        const int q0 = qt * 128;
        const int nt = qt + 1;

        load_kv(0, 0);

        uint32_t qa[8][4];
#pragma unroll
        for (int s = 0; s < 8; s++) {
            const float* qp = g_Q + ((size_t)(b * S + q0 + wb + p4)) * 64 + s * 8 + 2 * q4;
            float2 lo = *(const float2*)qp;
            float2 hi = *(const float2*)(qp + 8 * 64);
            qa[s][0] = f2u(lo.x);
            qa[s][1] = f2u(hi.x);
            qa[s][2] = f2u(lo.y);
            qa[s][3] = f2u(hi.y);
        }

        float of[8][4];
        float m0r = NEG, m1r = NEG, l0 = 0.0f, l1 = 0.0f;
#pragma unroll
        for (int j = 0; j < 8; j++)
#pragma unroll
            for (int e = 0; e < 4; e++) of[j][e] = 0.0f;

        for (int it = 0; it < nt; ++it) {
            const int st = it & 1;
            cpa_wait<0>();
            BAR_SYNC(barid);
            if (it + 1 < nt) load_kv(it + 1, st ^ 1);

            if (it == qt && kb > wb + 15) continue;   // fully-masked quarter

            const float* Ks  = sm + st * STG;
            const float* VTs = Ks + KSZ;

            float sf[8][4];
#pragma unroll
            for (int j = 0; j < 8; j++)
#pragma unroll
                for (int e = 0; e < 4; e++) sf[j][e] = 0.0f;

            const float* kB = Ks + (kb + p4) * 72 + 2 * q4;
#pragma unroll
            for (int s = 0; s < 8; s++) {
                const float* kp = kB + s * 8;
#pragma unroll
                for (int j = 0; j < 8; j++) {
                    float2 kv2 = *(const float2*)(kp + j * 8 * 72);
                    mma8(sf[j], qa[s], f2u(kv2.x), f2u(kv2.y));
                }
            }

            if (it == qt) {
                int r0 = wb + p4;
#pragma unroll
                for (int j = 0; j < 8; j++) {
                    int ta = kb + j * 8 + q4;
                    int tb = ta + 4;
                    if (ta > r0)     sf[j][0] = NEG;
                    if (tb > r0)     sf[j][1] = NEG;
                    if (ta > r0 + 8) sf[j][2] = NEG;
                    if (tb > r0 + 8) sf[j][3] = NEG;
                }
            }

            float mx0 = NEG, mx1 = NEG;
#pragma unroll
            for (int j = 0; j < 8; j++) {
                mx0 = fmaxf(mx0, fmaxf(sf[j][0], sf[j][1]));
                mx1 = fmaxf(mx1, fmaxf(sf[j][2], sf[j][3]));
            }
            mx0 = fmaxf(mx0, __shfl_xor_sync(0xffffffffu, mx0, 1));
            mx0 = fmaxf(mx0, __shfl_xor_sync(0xffffffffu, mx0, 2));
            mx1 = fmaxf(mx1, __shfl_xor_sync(0xffffffffu, mx1, 1));
            mx1 = fmaxf(mx1, __shfl_xor_sync(0xffffffffu, mx1, 2));
            float mn0 = fmaxf(m0r, mx0), mn1 = fmaxf(m1r, mx1);
            float al0 = ex2f(m0r - mn0), al1 = ex2f(m1r - mn1);
            m0r = mn0; m1r = mn1;
#pragma unroll
            for (int j = 0; j < 8; j++) {
                of[j][0] *= al0; of[j][1] *= al0;
                of[j][2] *= al1; of[j][3] *= al1;
            }

            float rs0 = 0.0f, rs1 = 0.0f;
            const float* vB = VTs + p4 * 136 + kb + 2 * q4;
#pragma unroll
            for (int s2 = 0; s2 < 8; s2++) {
                float p00 = tf32ef(ex2f(sf[s2][0] - mn0));
                float p01 = tf32ef(ex2f(sf[s2][1] - mn0));
                float p10 = tf32ef(ex2f(sf[s2][2] - mn1));
                float p11 = tf32ef(ex2f(sf[s2][3] - mn1));
                rs0 += p00 + p01;
                rs1 += p10 + p11;
                uint32_t pa[4];
                pa[0] = f2u(p00); pa[1] = f2u(p10);
                pa[2] = f2u(p01); pa[3] = f2u(p11);
                const float* vp = vB + s2 * 8;
#pragma unroll
                for (int j2 = 0; j2 < 8; j2++) {
                    float2 vv = *(const float2*)(vp + j2 * 8 * 136);
                    mma8(of[j2], pa, f2u(vv.x), f2u(vv.y));
                }
            }
            rs0 += __shfl_xor_sync(0xffffffffu, rs0, 1);
            rs0 += __shfl_xor_sync(0xffffffffu, rs0, 2);
            rs1 += __shfl_xor_sync(0xffffffffu, rs1, 1);
            rs1 += __shfl_xor_sync(0xffffffffu, rs1, 2);
            l0 = l0 * al0 + rs0;
            l1 = l1 * al1 + rs1;
        }

        __syncthreads();
        if (wc == 1) {
            float* cb = Cs + (wb + p4) * 132 + 2 * q4;
#pragma unroll
            for (int j2 = 0; j2 < 8; j2++) {
                *(float2*)(cb + j2 * 8)           = make_float2(of[j2][0], of[j2][1]);
                *(float2*)(cb + 8 * 132 + j2 * 8) = make_float2(of[j2][2], of[j2][3]);
            }
            if (q4 == 0) {
                Xm[wb + p4]     = m0r;  Xl[wb + p4]     = l0;
                Xm[wb + p4 + 8] = m1r;  Xl[wb + p4 + 8] = l1;
            }
        }
        __syncthreads();
        if (wc == 0) {
            float mo0 = Xm[wb + p4],     lo0 = Xl[wb + p4];
            float mo1 = Xm[wb + p4 + 8], lo1 = Xl[wb + p4 + 8];
            float mg0 = fmaxf(m0r, mo0), mg1 = fmaxf(m1r, mo1);
            float s0 = ex2f(m0r - mg0), t0 = ex2f(mo0 - mg0);
            float s1 = ex2f(m1r - mg1), t1 = ex2f(mo1 - mg1);
            float inv0 = 1.0f / (l0 * s0 + lo0 * t0);
            float inv1 = 1.0f / (l1 * s1 + lo1 * t1);
            const float* cb = Cs + (wb + p4) * 132 + 2 * q4;
            float* orow0 = out + ((size_t)(b * S + q0 + wb + p4)) * 64 + 2 * q4;
            float* orow1 = orow0 + 8 * 64;
#pragma unroll
            for (int j2 = 0; j2 < 8; j2++) {
                float2 c0 = *(const float2*)(cb + j2 * 8);
                float2 c1 = *(const float2*)(cb + 8 * 132 + j2 * 8);
                *(float2*)(orow0 + j2 * 8) =
                    make_float2((of[j2][0] * s0 + c0.x * t0) * inv0,
                                (of[j2][1] * s0 + c0.y * t0) * inv0);
                *(float2*)(orow1 + j2 * 8) =
                    make_float2((of[j2][2] * s1 + c1.x * t1) * inv1,
                                (of[j2][3] * s1 + c1.y * t1) * inv1);
            }
        }
        __syncthreads();
    }
}

// ---------------------------------------------------------------------------
extern "C" void kernel_launch(void* const* d_in, const int* in_sizes, int n_in,
                              void* d_out, int out_size)
{
    const float* x  = (const float*)d_in[0];
    const float* wq = (const float*)d_in[1];
    const float* wk = (const float*)d_in[2];
    const float* wv = (const float*)d_in[3];
    float* out = (float*)d_out;

    cudaFuncSetAttribute(proj_kernel,
                         cudaFuncAttributeMaxDynamicSharedMemorySize, PROJ_SMEM);
    cudaFuncSetAttribute(attn_kernel,
                         cudaFuncAttributeMaxDynamicSharedMemorySize, ATTN_SMEM);

    w_round_kernel<<<192, 256>>>(wq, wk, wv);
    proj_kernel<<<M / 128, 256, PROJ_SMEM>>>(x);
    attn_kernel<<<dim3(16, B), 512, ATTN_SMEM>>>(out);
}